// round 2
// baseline (speedup 1.0000x reference)
#include <cuda_runtime.h>
#include <math.h>
#include <float.h>

#define BATCH 256
#define NEXP  200000
#define DIM   128
#define DS    96
#define DA    32

// ---------------- scratch (static device globals; no runtime alloc) ----------
__device__ float g_aw[BATCH * DIM];            // agent * 1/std^2
__device__ float g_a2w[BATCH];                 // sum a^2/std^2
__device__ float g_e2w[NEXP];                  // sum e^2/std^2
__device__ float g_d2[(size_t)BATCH * NEXP];   // 204.8 MB pairwise d^2

// ---------------- f32x2 helpers ----------------
__device__ __forceinline__ unsigned long long pk2(float lo, float hi) {
    unsigned long long r;
    asm("mov.b64 %0, {%1,%2};" : "=l"(r) : "f"(lo), "f"(hi));
    return r;
}
__device__ __forceinline__ void fma2(unsigned long long& d, unsigned long long a, unsigned long long b) {
    asm("fma.rn.f32x2 %0, %1, %2, %0;" : "+l"(d) : "l"(a), "l"(b));
}
__device__ __forceinline__ float2 upk2(unsigned long long v) {
    float lo, hi;
    asm("mov.b64 {%0,%1}, %2;" : "=f"(lo), "=f"(hi) : "l"(v));
    return make_float2(lo, hi);
}

// ---------------- K0: agent prep ----------------
__global__ void prep_agent_kernel(const float* __restrict__ state,
                                  const float* __restrict__ action,
                                  const float* __restrict__ sstd) {
    __shared__ float red[DIM];
    int b = blockIdx.x, d = threadIdx.x;
    float a = (d < DS) ? state[b * DS + d] : action[b * DA + (d - DS)];
    float s = sstd[d];
    float inv = 1.0f / (s * s);
    float awv = a * inv;
    g_aw[b * DIM + d] = awv;
    red[d] = awv * a;
    __syncthreads();
    for (int off = 64; off > 0; off >>= 1) {
        if (d < off) red[d] += red[d + off];
        __syncthreads();
    }
    if (d == 0) g_a2w[b] = red[0];
}

// ---------------- K1: expert weighted norms ----------------
__global__ void prep_e2w_kernel(const float* __restrict__ experts,
                                const float* __restrict__ sstd) {
    __shared__ __align__(16) float inv[DIM];
    int t = threadIdx.x;
    if (t < DIM) { float s = sstd[t]; inv[t] = 1.0f / (s * s); }
    __syncthreads();
    int lane = t & 31, warp = t >> 5;
    int n = blockIdx.x * 8 + warp;          // grid = NEXP/8 exactly
    float4 e = ((const float4*)(experts + (size_t)n * DIM))[lane];
    float4 w = ((const float4*)inv)[lane];
    float s = e.x * e.x * w.x + e.y * e.y * w.y + e.z * e.z * w.z + e.w * e.w * w.w;
    #pragma unroll
    for (int off = 16; off; off >>= 1) s += __shfl_xor_sync(0xffffffffu, s, off);
    if (lane == 0) g_e2w[n] = s;
}

// ---------------- K2: SGEMM -> d^2 ----------------
#define BB 128
#define BN 128
#define PITCH 132   // 128 + 4 pad, keeps float4 alignment, spreads banks

__global__ void __launch_bounds__(256, 1)
gemm_d2_kernel(const float* __restrict__ experts) {
    extern __shared__ float sh[];
    float* As = sh;                 // [BB][PITCH] agents (aw), natural layout
    float* Es = sh + BB * PITCH;    // [BN][PITCH] experts, natural layout
    const int tid = threadIdx.x;
    const int tx = tid & 15, ty = tid >> 4;
    const int n0 = blockIdx.x * BN;
    const int b0 = blockIdx.y * BB;

    // load A tile (128 rows x 128 floats), coalesced float4
    #pragma unroll
    for (int it = 0; it < 16; it++) {
        int idx = tid + 256 * it;
        int r = idx >> 5, c = idx & 31;
        float4 v = *((const float4*)(g_aw + (size_t)(b0 + r) * DIM + c * 4));
        *((float4*)(As + r * PITCH + c * 4)) = v;
    }
    // load E tile with bounds guard (last tile has 64 valid rows)
    #pragma unroll
    for (int it = 0; it < 16; it++) {
        int idx = tid + 256 * it;
        int r = idx >> 5, c = idx & 31;
        int n = n0 + r;
        float4 v = make_float4(0.f, 0.f, 0.f, 0.f);
        if (n < NEXP) v = *((const float4*)(experts + (size_t)n * DIM + c * 4));
        *((float4*)(Es + r * PITCH + c * 4)) = v;
    }
    __syncthreads();

    // 8 agents (contiguous, broadcast LDS) x 8 experts (stride 16 in n)
    unsigned long long acc[4][8];
    #pragma unroll
    for (int p = 0; p < 4; p++)
        #pragma unroll
        for (int j = 0; j < 8; j++) acc[p][j] = 0ull;

    const float* Ab = As + (ty * 8) * PITCH;
    const float* Eb = Es + tx * PITCH;

    #pragma unroll 4
    for (int k = 0; k < DIM; k++) {
        float av[8];
        #pragma unroll
        for (int i = 0; i < 8; i++) av[i] = Ab[i * PITCH + k];
        unsigned long long ap[4];
        #pragma unroll
        for (int p = 0; p < 4; p++) ap[p] = pk2(av[2 * p], av[2 * p + 1]);
        #pragma unroll
        for (int j = 0; j < 8; j++) {
            float e = Eb[(16 * j) * PITCH + k];
            unsigned long long ed = pk2(e, e);
            #pragma unroll
            for (int p = 0; p < 4; p++) fma2(acc[p][j], ap[p], ed);
        }
    }

    // epilogue: d2 = a2w + e2w - 2*dot, clamped
    float a2[8];
    #pragma unroll
    for (int i = 0; i < 8; i++) a2[i] = g_a2w[b0 + ty * 8 + i];
    #pragma unroll
    for (int j = 0; j < 8; j++) {
        int n = n0 + tx + 16 * j;
        if (n >= NEXP) continue;
        float e2 = g_e2w[n];
        #pragma unroll
        for (int p = 0; p < 4; p++) {
            float2 c = upk2(acc[p][j]);
            int bA = b0 + ty * 8 + 2 * p;
            g_d2[(size_t)bA * NEXP + n]       = fmaxf(a2[2 * p]     + e2 - 2.0f * c.x, 1e-12f);
            g_d2[(size_t)(bA + 1) * NEXP + n] = fmaxf(a2[2 * p + 1] + e2 - 2.0f * c.y, 1e-12f);
        }
    }
}

// ---------------- K3: per-row top-200 selection + reward ----------------
#define SELT 512
#define KLOC 16

__global__ void __launch_bounds__(SELT)
select_kernel(const float* __restrict__ wts, float* __restrict__ out) {
    __shared__ float cand[KLOC * SELT];     // [slot][thread] -> bank = tid%32
    __shared__ unsigned int hist[256];
    __shared__ unsigned int s_pref;
    __shared__ int s_rank;
    __shared__ float s_f[SELT];
    __shared__ int   s_i[SELT];
    __shared__ float s_w;
    __shared__ double s_r;
    __shared__ int s_m;

    const int b = blockIdx.x, t = threadIdx.x;
    #pragma unroll
    for (int s = 0; s < KLOC; s++) cand[s * SELT + t] = FLT_MAX;
    float curmax = FLT_MAX; int maxslot = 0;

    // stream row, keep per-thread 16 smallest
    const float4* row = (const float4*)(g_d2 + (size_t)b * NEXP);
    const int n4 = NEXP / 4;   // 50000 exact
    for (int i = t; i < n4; i += SELT) {
        float4 v = row[i];
        float vv[4] = {v.x, v.y, v.z, v.w};
        #pragma unroll
        for (int q = 0; q < 4; q++) {
            if (vv[q] < curmax) {
                cand[maxslot * SELT + t] = vv[q];
                curmax = -FLT_MAX;
                #pragma unroll
                for (int s = 0; s < KLOC; s++) {
                    float cs = cand[s * SELT + t];
                    if (cs > curmax) { curmax = cs; maxslot = s; }
                }
            }
        }
    }

    if (t == 0) {
        float w = wts[0];
        double targ = 1.0 / 1000.0 - 1e-6;
        int m = (int)(targ / (double)w);          // # fully-consumed atoms (199)
        double r = targ - (double)m * (double)w;  // partial mass on rank m (4e-6)
        if (r <= 0.0) { m -= 1; r = (double)w; }
        s_w = w; s_m = m; s_r = r;
        s_pref = 0u; s_rank = m;
    }
    __syncthreads();

    // exact MSD radix-select of the rank-m value over 8192 candidates
    for (int pass = 3; pass >= 0; pass--) {
        int shift = pass * 8;
        if (t < 256) hist[t] = 0u;
        __syncthreads();
        unsigned int pref = s_pref;
        #pragma unroll
        for (int s = 0; s < KLOC; s++) {
            unsigned int key = __float_as_uint(cand[s * SELT + t]);  // d2 >= 0 -> monotone bits
            if (((key >> shift) >> 8) == pref)
                atomicAdd(&hist[(key >> shift) & 255u], 1u);
        }
        __syncthreads();
        if (t == 0) {
            int r = s_rank;
            unsigned int cum = 0, bin = 0;
            for (bin = 0; bin < 256; bin++) {
                unsigned int h = hist[bin];
                if (cum + h > (unsigned)r) break;
                cum += h;
            }
            s_rank = r - (int)cum;
            s_pref = (s_pref << 8) | bin;
        }
        __syncthreads();
    }

    unsigned int Tkey = s_pref;
    float Tval = __uint_as_float(Tkey);
    int c = 0; float ss = 0.0f;
    #pragma unroll
    for (int s = 0; s < KLOC; s++) {
        float v = cand[s * SELT + t];
        if (__float_as_uint(v) < Tkey) { c++; ss += sqrtf(v); }
    }
    s_f[t] = ss; s_i[t] = c;
    __syncthreads();
    for (int off = SELT / 2; off > 0; off >>= 1) {
        if (t < off) { s_f[t] += s_f[t + off]; s_i[t] += s_i[t + off]; }
        __syncthreads();
    }
    if (t == 0) {
        double w = (double)s_w;
        double dT = sqrt((double)Tval);
        double cost = w * (double)s_f[0] + (w * (double)(s_m - s_i[0]) + s_r) * dT;
        double BW = 5000.0 / sqrt(128.0);   // 5 * T / sqrt(D)
        out[b] = (float)(5.0 * exp(-BW * cost));
    }
}

// ---------------- launch ----------------
extern "C" void kernel_launch(void* const* d_in, const int* in_sizes, int n_in,
                              void* d_out, int out_size) {
    const float* state   = (const float*)d_in[0];
    const float* action  = (const float*)d_in[1];
    const float* experts = (const float*)d_in[2];
    const float* wts     = (const float*)d_in[3];
    // d_in[4] = scaler_mean: cancels algebraically, unused
    const float* sstd    = (const float*)d_in[5];
    float* out = (float*)d_out;

    prep_agent_kernel<<<BATCH, DIM>>>(state, action, sstd);
    prep_e2w_kernel<<<NEXP / 8, 256>>>(experts, sstd);

    size_t shbytes = (size_t)(BB + BN) * PITCH * sizeof(float);  // 135168
    cudaFuncSetAttribute(gemm_d2_kernel, cudaFuncAttributeMaxDynamicSharedMemorySize, (int)shbytes);
    dim3 grid((NEXP + BN - 1) / BN, BATCH / BB);
    gemm_d2_kernel<<<grid, 256, shbytes>>>(experts);

    select_kernel<<<BATCH, SELT>>>(wts, out);
}

// round 5
// speedup vs baseline: 3.3611x; 3.3611x over previous
#include <cuda_runtime.h>
#include <cuda_bf16.h>
#include <math.h>
#include <float.h>
#include <stdint.h>

#define BATCH 256
#define NEXP  200000
#define DIM   128
#define DS    96
#define DA    32

#define TILE_N   128
#define NTILES   1563                 // ceil(200000/128)
#define NPAD     (NTILES * TILE_N)    // 200064
#define STILES   98
#define SAMPLE_N (STILES * TILE_N)    // 12544
#define SRANK    63                   // 0-based sample rank for threshold
#define SLOTS    12
#define CANDTOT  (NTILES * SLOTS)     // 18756

#define PITCH 136                     // bf16 elems per smem row (128 + 8 pad)

// ---------------- static device scratch ----------------
__device__ float          g_a2w[BATCH];
__device__ __nv_bfloat16  g_abf[BATCH * DIM];            // (a/s^2) in bf16
__device__ __nv_bfloat16  g_ebf[(size_t)NPAD * DIM];     // raw experts bf16 (padded)
__device__ float          g_e2w[NPAD];                   // sum e^2/s^2 (pad = 1e30)
__device__ float          g_d2s[(size_t)BATCH * SAMPLE_N];  // row-major [b][i]
__device__ float          g_thresh[BATCH];
__device__ float          g_cand[(size_t)NTILES * BATCH * SLOTS];

// ---------------- helpers ----------------
__device__ __forceinline__ uint32_t smem_u32(const void* p) {
    uint32_t a;
    asm("{ .reg .u64 t; cvta.to.shared.u64 t, %1; cvt.u32.u64 %0, t; }" : "=r"(a) : "l"(p));
    return a;
}
__device__ __forceinline__ void ldm_x4(uint32_t& r0, uint32_t& r1, uint32_t& r2, uint32_t& r3,
                                       uint32_t addr) {
    asm volatile("ldmatrix.sync.aligned.m8n8.x4.shared.b16 {%0,%1,%2,%3}, [%4];"
                 : "=r"(r0), "=r"(r1), "=r"(r2), "=r"(r3) : "r"(addr));
}
__device__ __forceinline__ void mma_bf16(float* d, const uint32_t* a, const uint32_t* b) {
    asm volatile("mma.sync.aligned.m16n8k16.row.col.f32.bf16.bf16.f32 "
                 "{%0,%1,%2,%3}, {%4,%5,%6,%7}, {%8,%9}, {%0,%1,%2,%3};"
                 : "+f"(d[0]), "+f"(d[1]), "+f"(d[2]), "+f"(d[3])
                 : "r"(a[0]), "r"(a[1]), "r"(a[2]), "r"(a[3]), "r"(b[0]), "r"(b[1]));
}

// ---------------- K0: agent prep ----------------
__global__ void prep_agent_kernel(const float* __restrict__ state,
                                  const float* __restrict__ action,
                                  const float* __restrict__ sstd) {
    __shared__ float red[DIM];
    int b = blockIdx.x, d = threadIdx.x;
    float a = (d < DS) ? state[b * DS + d] : action[b * DA + (d - DS)];
    float s = sstd[d];
    float inv = 1.0f / (s * s);
    float awv = a * inv;
    g_abf[b * DIM + d] = __float2bfloat16_rn(awv);
    red[d] = awv * a;
    __syncthreads();
    for (int off = 64; off > 0; off >>= 1) {
        if (d < off) red[d] += red[d + off];
        __syncthreads();
    }
    if (d == 0) g_a2w[b] = red[0];
}

// ---------------- K1: expert bf16 convert + weighted norms ----------------
__global__ void prep_experts_kernel(const float* __restrict__ experts,
                                    const float* __restrict__ sstd) {
    __shared__ __align__(16) float inv[DIM];
    int t = threadIdx.x;
    if (t < DIM) { float s = sstd[t]; inv[t] = 1.0f / (s * s); }
    __syncthreads();
    int lane = t & 31, warp = t >> 5;
    int n = blockIdx.x * 8 + warp;                 // grid = NPAD/8
    float4 e = make_float4(0.f, 0.f, 0.f, 0.f);
    if (n < NEXP) e = ((const float4*)(experts + (size_t)n * DIM))[lane];
    float4 w = ((const float4*)inv)[lane];
    float s = e.x * e.x * w.x + e.y * e.y * w.y + e.z * e.z * w.z + e.w * e.w * w.w;
    #pragma unroll
    for (int off = 16; off; off >>= 1) s += __shfl_xor_sync(0xffffffffu, s, off);
    if (lane == 0) g_e2w[n] = (n < NEXP) ? s : 1e30f;
    __nv_bfloat162* dst = reinterpret_cast<__nv_bfloat162*>(g_ebf + (size_t)n * DIM);
    dst[2 * lane]     = __floats2bfloat162_rn(e.x, e.y);
    dst[2 * lane + 1] = __floats2bfloat162_rn(e.z, e.w);
}

// ---------------- K2: HMMA bf16 GEMM (mode 0: sample d2, mode 1: filtered) ----
// smem layout (bytes)
#define OFF_A    0
#define OFF_B    (128 * PITCH * 2)            // 34816
#define OFF_E2   (2 * 128 * PITCH * 2)        // 69632
#define OFF_A2   (OFF_E2 + 512)
#define OFF_TH   (OFF_A2 + 512)
#define OFF_CNT  (OFF_TH + 512)
#define OFF_CAND (OFF_CNT + 512)
#define GEMM_SMEM (OFF_CAND + 128 * SLOTS * 4)  // 77824

__global__ void __launch_bounds__(256, 2)
gemm_kernel(int mode) {
    extern __shared__ __align__(16) char sm[];
    const uint32_t smb = smem_u32(sm);
    const int tid = threadIdx.x, w = tid >> 5, lane = tid & 31;
    const int hid = blockIdx.x;                // agent half: 0 or 1
    const int tile = blockIdx.y;
    const int n0 = tile * TILE_N;

    float* e2s  = (float*)(sm + OFF_E2);
    float* a2s  = (float*)(sm + OFF_A2);
    float* ths  = (float*)(sm + OFF_TH);
    int*   scnt = (int*)(sm + OFF_CNT);
    float* scand = (float*)(sm + OFF_CAND);

    // ---- load tiles: 2 threads per row, 128B each (full 256B row) ----
    {
        int r = tid >> 1, h = (tid & 1) * 8;   // h: starting uint4 index (0 or 8)
        const uint4* asrc = (const uint4*)(g_abf + (size_t)(hid * 128 + r) * DIM) + h;
        const uint4* bsrc = (const uint4*)(g_ebf + (size_t)(n0 + r) * DIM) + h;
        uint4* adst = (uint4*)(sm + OFF_A + r * PITCH * 2 + h * 16);
        uint4* bdst = (uint4*)(sm + OFF_B + r * PITCH * 2 + h * 16);
        #pragma unroll
        for (int i = 0; i < 8; i++) { adst[i] = asrc[i]; bdst[i] = bsrc[i]; }
    }
    if (tid < 128) {
        e2s[tid] = g_e2w[n0 + tid];
        a2s[tid] = g_a2w[hid * 128 + tid];
        ths[tid] = g_thresh[hid * 128 + tid];
        scnt[tid] = 0;
    }
    #pragma unroll
    for (int s = tid; s < 128 * SLOTS; s += 256) scand[s] = FLT_MAX;
    __syncthreads();

    // ---- warp tile: 32 (M) x 64 (N); warps 4x2 ----
    const int mbase = (w >> 1) * 32, nbase = (w & 1) * 64;

    // ldmatrix base addresses
    const uint32_t a_addr0 = smb + OFF_A +
        (uint32_t)(((mbase + (lane & 15)) * PITCH + (lane >> 4) * 8) * 2);
    const uint32_t b_addr0 = smb + OFF_B +
        (uint32_t)(((nbase + (lane >> 4) * 8 + (lane & 7)) * PITCH + ((lane >> 3) & 1) * 8) * 2);

    float acc[2][8][4];
    #pragma unroll
    for (int mf = 0; mf < 2; mf++)
        #pragma unroll
        for (int j = 0; j < 8; j++)
            #pragma unroll
            for (int q = 0; q < 4; q++) acc[mf][j][q] = 0.f;

    #pragma unroll
    for (int k = 0; k < 8; k++) {
        const uint32_t koff = (uint32_t)(k * 32);   // 16 bf16 = 32B
        uint32_t A[2][4];
        ldm_x4(A[0][0], A[0][1], A[0][2], A[0][3], a_addr0 + koff);
        ldm_x4(A[1][0], A[1][1], A[1][2], A[1][3], a_addr0 + koff + 16 * PITCH * 2);
        uint32_t Bf[8][2];
        #pragma unroll
        for (int jj = 0; jj < 4; jj++) {
            uint32_t r0, r1, r2, r3;
            ldm_x4(r0, r1, r2, r3, b_addr0 + koff + (uint32_t)(jj * 16 * PITCH * 2));
            Bf[jj * 2][0] = r0; Bf[jj * 2][1] = r1;
            Bf[jj * 2 + 1][0] = r2; Bf[jj * 2 + 1][1] = r3;
        }
        #pragma unroll
        for (int mf = 0; mf < 2; mf++)
            #pragma unroll
            for (int j = 0; j < 8; j++)
                mma_bf16(acc[mf][j], A[mf], Bf[j]);
    }

    // ---- epilogue ----
    const int c0 = nbase + (lane & 3) * 2;
    #pragma unroll
    for (int mf = 0; mf < 2; mf++) {
        #pragma unroll
        for (int hr = 0; hr < 2; hr++) {
            const int rl = mbase + mf * 16 + (lane >> 2) + hr * 8;   // local agent row
            const float a2 = a2s[rl];
            const int agent = hid * 128 + rl;
            if (mode == 0) {
                float* dst = g_d2s + (size_t)agent * SAMPLE_N + n0;
                #pragma unroll
                for (int j = 0; j < 8; j++) {
                    const int col = c0 + j * 8;
                    float d2a = fmaxf(a2 + e2s[col]     - 2.0f * acc[mf][j][hr * 2],     1e-12f);
                    float d2b = fmaxf(a2 + e2s[col + 1] - 2.0f * acc[mf][j][hr * 2 + 1], 1e-12f);
                    *(float2*)(dst + col) = make_float2(d2a, d2b);
                }
            } else {
                const float T = ths[rl];
                #pragma unroll
                for (int j = 0; j < 8; j++) {
                    const int col = c0 + j * 8;
                    float d2a = fmaxf(a2 + e2s[col]     - 2.0f * acc[mf][j][hr * 2],     1e-12f);
                    float d2b = fmaxf(a2 + e2s[col + 1] - 2.0f * acc[mf][j][hr * 2 + 1], 1e-12f);
                    if (d2a < T) { int p = atomicAdd(&scnt[rl], 1); if (p < SLOTS) scand[rl * SLOTS + p] = d2a; }
                    if (d2b < T) { int p = atomicAdd(&scnt[rl], 1); if (p < SLOTS) scand[rl * SLOTS + p] = d2b; }
                }
            }
        }
    }

    if (mode == 1) {
        __syncthreads();
        if (tid < 128) {
            const int agent = hid * 128 + tid;
            uint4* dst = (uint4*)(g_cand + ((size_t)tile * BATCH + agent) * SLOTS);
            const uint4* src = (const uint4*)(scand + tid * SLOTS);
            #pragma unroll
            for (int i = 0; i < SLOTS / 4; i++) dst[i] = src[i];
        }
    }
}

// ---------------- K3: per-row sample threshold (radix-select rank SRANK) -----
__global__ void __launch_bounds__(256) thresh_kernel() {
    extern __shared__ float sv[];  // SAMPLE_N floats
    __shared__ unsigned int hist[256];
    __shared__ unsigned int s_pref;
    __shared__ int s_rank;
    const int b = blockIdx.x, t = threadIdx.x;
    for (int i = t; i < SAMPLE_N; i += 256) sv[i] = g_d2s[(size_t)b * SAMPLE_N + i];
    if (t == 0) { s_pref = 0u; s_rank = SRANK; }
    __syncthreads();
    for (int pass = 3; pass >= 0; pass--) {
        int shift = pass * 8;
        hist[t] = 0u;
        __syncthreads();
        unsigned int pref = s_pref;
        for (int i = t; i < SAMPLE_N; i += 256) {
            unsigned int key = __float_as_uint(sv[i]);
            if (((key >> shift) >> 8) == pref)
                atomicAdd(&hist[(key >> shift) & 255u], 1u);
        }
        __syncthreads();
        if (t == 0) {
            int r = s_rank;
            unsigned int cum = 0, bin = 0;
            for (bin = 0; bin < 256; bin++) {
                unsigned int h = hist[bin];
                if (cum + h > (unsigned)r) break;
                cum += h;
            }
            s_rank = r - (int)cum;
            s_pref = (s_pref << 8) | bin;
        }
        __syncthreads();
    }
    if (t == 0) g_thresh[b] = __uint_as_float(s_pref);
}

// ---------------- K4: final exact select over candidates + reward -----------
__global__ void __launch_bounds__(256) final_kernel(const float* __restrict__ wts,
                                                    float* __restrict__ out) {
    extern __shared__ float sv[];  // CANDTOT floats
    __shared__ unsigned int hist[256];
    __shared__ unsigned int s_pref;
    __shared__ int s_rank;
    __shared__ float s_f[256];
    __shared__ int s_i[256];
    __shared__ float s_w;
    __shared__ double s_r;
    __shared__ int s_m;
    const int b = blockIdx.x, t = threadIdx.x;

    for (int i = t; i < CANDTOT; i += 256) {
        int tl = i / SLOTS, s = i % SLOTS;
        sv[i] = g_cand[((size_t)tl * BATCH + b) * SLOTS + s];
    }
    if (t == 0) {
        float w = wts[0];
        double targ = 1.0 / 1000.0 - 1e-6;
        int m = (int)(targ / (double)w);
        double r = targ - (double)m * (double)w;
        if (r <= 0.0) { m -= 1; r = (double)w; }
        s_w = w; s_m = m; s_r = r;
        s_pref = 0u; s_rank = m;
    }
    __syncthreads();

    for (int pass = 3; pass >= 0; pass--) {
        int shift = pass * 8;
        hist[t] = 0u;
        __syncthreads();
        unsigned int pref = s_pref;
        for (int i = t; i < CANDTOT; i += 256) {
            unsigned int key = __float_as_uint(sv[i]);
            if (((key >> shift) >> 8) == pref)
                atomicAdd(&hist[(key >> shift) & 255u], 1u);
        }
        __syncthreads();
        if (t == 0) {
            int r = s_rank;
            unsigned int cum = 0, bin = 0;
            for (bin = 0; bin < 256; bin++) {
                unsigned int h = hist[bin];
                if (cum + h > (unsigned)r) break;
                cum += h;
            }
            s_rank = r - (int)cum;
            s_pref = (s_pref << 8) | bin;
        }
        __syncthreads();
    }

    unsigned int Tkey = s_pref;
    float Tval = __uint_as_float(Tkey);
    int c = 0;
    float ss = 0.0f;
    for (int i = t; i < CANDTOT; i += 256) {
        float v = sv[i];
        if (__float_as_uint(v) < Tkey) { c++; ss += sqrtf(v); }
    }
    s_f[t] = ss; s_i[t] = c;
    __syncthreads();
    for (int off = 128; off > 0; off >>= 1) {
        if (t < off) { s_f[t] += s_f[t + off]; s_i[t] += s_i[t + off]; }
        __syncthreads();
    }
    if (t == 0) {
        double w = (double)s_w;
        double dT = sqrt((double)Tval);
        double cost = w * (double)s_f[0] + (w * (double)(s_m - s_i[0]) + s_r) * dT;
        double BW = 5000.0 / sqrt(128.0);
        out[b] = (float)(5.0 * exp(-BW * cost));
    }
}

// ---------------- launch ----------------
extern "C" void kernel_launch(void* const* d_in, const int* in_sizes, int n_in,
                              void* d_out, int out_size) {
    const float* state   = (const float*)d_in[0];
    const float* action  = (const float*)d_in[1];
    const float* experts = (const float*)d_in[2];
    const float* wts     = (const float*)d_in[3];
    // d_in[4] = scaler_mean: cancels algebraically
    const float* sstd    = (const float*)d_in[5];
    float* out = (float*)d_out;

    cudaFuncSetAttribute(gemm_kernel,   cudaFuncAttributeMaxDynamicSharedMemorySize, GEMM_SMEM);
    cudaFuncSetAttribute(thresh_kernel, cudaFuncAttributeMaxDynamicSharedMemorySize, SAMPLE_N * 4);
    cudaFuncSetAttribute(final_kernel,  cudaFuncAttributeMaxDynamicSharedMemorySize, CANDTOT * 4);

    prep_agent_kernel<<<BATCH, DIM>>>(state, action, sstd);
    prep_experts_kernel<<<NPAD / 8, 256>>>(experts, sstd);
    gemm_kernel<<<dim3(2, STILES), 256, GEMM_SMEM>>>(0);
    thresh_kernel<<<BATCH, 256, SAMPLE_N * 4>>>();
    gemm_kernel<<<dim3(2, NTILES), 256, GEMM_SMEM>>>(1);
    final_kernel<<<BATCH, 256, CANDTOT * 4>>>(wts, out);
}

// round 6
// speedup vs baseline: 3.4301x; 1.0205x over previous
#include <cuda_runtime.h>
#include <cuda_bf16.h>
#include <math.h>
#include <float.h>
#include <stdint.h>

#define BATCH 256
#define NEXP  200000
#define DIM   128
#define DS    96
#define DA    32

#define TILE_N   128
#define NTILES   1563                 // ceil(200000/128)
#define STILES   98
#define SAMPLE_N (STILES * TILE_N)    // 12544
#define SRANK    63                   // 0-based sample rank for threshold
#define SLOTS    12
#define CANDTOT  (NTILES * SLOTS)     // 18756

#define PITCH 136                     // bf16 elems per smem row (128 + 8 pad)

// ---------------- static device scratch ----------------
__device__ float          g_a2w[BATCH];
__device__ float          g_inv[DIM];                    // 1/std^2
__device__ __nv_bfloat16  g_abf[BATCH * DIM];            // (a/s^2) in bf16
__device__ float          g_d2s[(size_t)BATCH * SAMPLE_N];  // row-major [b][i]
__device__ float          g_thresh[BATCH];
__device__ float          g_cand[(size_t)NTILES * BATCH * SLOTS];

// ---------------- helpers ----------------
__device__ __forceinline__ uint32_t smem_u32(const void* p) {
    uint32_t a;
    asm("{ .reg .u64 t; cvta.to.shared.u64 t, %1; cvt.u32.u64 %0, t; }" : "=r"(a) : "l"(p));
    return a;
}
__device__ __forceinline__ void ldm_x4(uint32_t& r0, uint32_t& r1, uint32_t& r2, uint32_t& r3,
                                       uint32_t addr) {
    asm volatile("ldmatrix.sync.aligned.m8n8.x4.shared.b16 {%0,%1,%2,%3}, [%4];"
                 : "=r"(r0), "=r"(r1), "=r"(r2), "=r"(r3) : "r"(addr));
}
__device__ __forceinline__ void mma_bf16(float* d, const uint32_t* a, const uint32_t* b) {
    asm volatile("mma.sync.aligned.m16n8k16.row.col.f32.bf16.bf16.f32 "
                 "{%0,%1,%2,%3}, {%4,%5,%6,%7}, {%8,%9}, {%0,%1,%2,%3};"
                 : "+f"(d[0]), "+f"(d[1]), "+f"(d[2]), "+f"(d[3])
                 : "r"(a[0]), "r"(a[1]), "r"(a[2]), "r"(a[3]), "r"(b[0]), "r"(b[1]));
}
__device__ __forceinline__ uint32_t bf2u(float lo, float hi) {
    __nv_bfloat162 b = __floats2bfloat162_rn(lo, hi);
    return *reinterpret_cast<uint32_t*>(&b);
}

// parallel radix-select step: hist[256] filled; update (pref, rank) for this byte.
// Must be called by all 256 threads.
__device__ __forceinline__ void radix_pass(unsigned int* hist, unsigned int* s_pref,
                                           int* s_rank, int t) {
    __shared__ unsigned int wsum[8];
    const int lane = t & 31, wp = t >> 5;
    unsigned int v = hist[t];
    unsigned int inc = v;
    #pragma unroll
    for (int o = 1; o < 32; o <<= 1) {
        unsigned int u = __shfl_up_sync(0xffffffffu, inc, o);
        if (lane >= o) inc += u;
    }
    if (lane == 31) wsum[wp] = inc;
    __syncthreads();
    unsigned int base = 0;
    #pragma unroll
    for (int i = 0; i < 8; i++) if (i < wp) base += wsum[i];
    const unsigned int incl = inc + base;
    const unsigned int excl = incl - v;
    const int r = *s_rank;
    __syncthreads();
    if ((unsigned)r >= excl && (unsigned)r < incl) {
        *s_rank = r - (int)excl;
        *s_pref = (*s_pref << 8) | (unsigned)t;
    }
    __syncthreads();
}

// ---------------- K0: agent prep ----------------
__global__ void prep_agent_kernel(const float* __restrict__ state,
                                  const float* __restrict__ action,
                                  const float* __restrict__ sstd) {
    __shared__ float red[DIM];
    int b = blockIdx.x, d = threadIdx.x;
    float a = (d < DS) ? state[b * DS + d] : action[b * DA + (d - DS)];
    float s = sstd[d];
    float inv = 1.0f / (s * s);
    float awv = a * inv;
    g_abf[b * DIM + d] = __float2bfloat16_rn(awv);
    if (b == 0) g_inv[d] = inv;
    red[d] = awv * a;
    __syncthreads();
    for (int off = 64; off > 0; off >>= 1) {
        if (d < off) red[d] += red[d + off];
        __syncthreads();
    }
    if (d == 0) g_a2w[b] = red[0];
}

// ---------------- K2: HMMA bf16 GEMM (mode 0: sample d2, mode 1: filtered) ----
// smem layout (bytes)
#define OFF_A    0
#define OFF_B    (128 * PITCH * 2)            // 34816
#define OFF_E2   (2 * 128 * PITCH * 2)        // 69632
#define OFF_A2   (OFF_E2 + 512)
#define OFF_TH   (OFF_A2 + 512)
#define OFF_CNT  (OFF_TH + 512)
#define OFF_CAND (OFF_CNT + 512)
#define GEMM_SMEM (OFF_CAND + 128 * SLOTS * 4)  // 77824

__global__ void __launch_bounds__(256, 2)
gemm_kernel(const float* __restrict__ experts, int mode) {
    extern __shared__ __align__(16) char sm[];
    const uint32_t smb = smem_u32(sm);
    const int tid = threadIdx.x, w = tid >> 5, lane = tid & 31;
    const int hid = blockIdx.x;                // agent half: 0 or 1
    const int tile = blockIdx.y;
    const int n0 = tile * TILE_N;

    float* e2s  = (float*)(sm + OFF_E2);
    float* a2s  = (float*)(sm + OFF_A2);
    float* ths  = (float*)(sm + OFF_TH);
    int*   scnt = (int*)(sm + OFF_CNT);
    float* scand = (float*)(sm + OFF_CAND);

    // ---- A tile (bf16): 2 threads/row, 128B each ----
    {
        int r = tid >> 1, h = (tid & 1) * 8;
        const uint4* asrc = (const uint4*)(g_abf + (size_t)(hid * 128 + r) * DIM) + h;
        uint4* adst = (uint4*)(sm + OFF_A + r * PITCH * 2 + h * 16);
        #pragma unroll
        for (int i = 0; i < 8; i++) adst[i] = asrc[i];
    }
    // ---- E tile: fp32 -> bf16 convert + weighted norm, 2 threads/row ----
    {
        const int r = tid >> 1;
        const int cb = (tid & 1) * 64;             // starting float column
        const int n = n0 + r;
        const bool ok = (n < NEXP);
        const float4* esrc = (const float4*)(experts + (size_t)n * DIM + cb);
        const float4* ginv = (const float4*)(g_inv + cb);
        uint4* edst = (uint4*)(sm + OFF_B + r * PITCH * 2 + cb * 2);
        float part = 0.f;
        #pragma unroll
        for (int i = 0; i < 8; i++) {
            float4 f0 = ok ? __ldg(esrc + 2 * i)     : make_float4(0.f, 0.f, 0.f, 0.f);
            float4 f1 = ok ? __ldg(esrc + 2 * i + 1) : make_float4(0.f, 0.f, 0.f, 0.f);
            float4 w0 = __ldg(ginv + 2 * i);
            float4 w1 = __ldg(ginv + 2 * i + 1);
            part += f0.x * f0.x * w0.x + f0.y * f0.y * w0.y + f0.z * f0.z * w0.z + f0.w * f0.w * w0.w
                  + f1.x * f1.x * w1.x + f1.y * f1.y * w1.y + f1.z * f1.z * w1.z + f1.w * f1.w * w1.w;
            uint4 o;
            o.x = bf2u(f0.x, f0.y); o.y = bf2u(f0.z, f0.w);
            o.z = bf2u(f1.x, f1.y); o.w = bf2u(f1.z, f1.w);
            edst[i] = o;
        }
        part += __shfl_xor_sync(0xffffffffu, part, 1);
        if ((tid & 1) == 0) e2s[r] = ok ? part : 1e30f;
    }
    if (tid < 128) {
        a2s[tid] = g_a2w[hid * 128 + tid];
        ths[tid] = g_thresh[hid * 128 + tid];
        scnt[tid] = 0;
    }
    #pragma unroll
    for (int s = tid; s < 128 * SLOTS; s += 256) scand[s] = FLT_MAX;
    __syncthreads();

    // ---- warp tile: 32 (M) x 64 (N); warps 4x2 ----
    const int mbase = (w >> 1) * 32, nbase = (w & 1) * 64;

    const uint32_t a_addr0 = smb + OFF_A +
        (uint32_t)(((mbase + (lane & 15)) * PITCH + (lane >> 4) * 8) * 2);
    const uint32_t b_addr0 = smb + OFF_B +
        (uint32_t)(((nbase + (lane >> 4) * 8 + (lane & 7)) * PITCH + ((lane >> 3) & 1) * 8) * 2);

    float acc[2][8][4];
    #pragma unroll
    for (int mf = 0; mf < 2; mf++)
        #pragma unroll
        for (int j = 0; j < 8; j++)
            #pragma unroll
            for (int q = 0; q < 4; q++) acc[mf][j][q] = 0.f;

    #pragma unroll
    for (int k = 0; k < 8; k++) {
        const uint32_t koff = (uint32_t)(k * 32);   // 16 bf16 = 32B
        uint32_t A[2][4];
        ldm_x4(A[0][0], A[0][1], A[0][2], A[0][3], a_addr0 + koff);
        ldm_x4(A[1][0], A[1][1], A[1][2], A[1][3], a_addr0 + koff + 16 * PITCH * 2);
        uint32_t Bf[8][2];
        #pragma unroll
        for (int jj = 0; jj < 4; jj++) {
            uint32_t r0, r1, r2, r3;
            ldm_x4(r0, r1, r2, r3, b_addr0 + koff + (uint32_t)(jj * 16 * PITCH * 2));
            Bf[jj * 2][0] = r0; Bf[jj * 2][1] = r1;
            Bf[jj * 2 + 1][0] = r2; Bf[jj * 2 + 1][1] = r3;
        }
        #pragma unroll
        for (int mf = 0; mf < 2; mf++)
            #pragma unroll
            for (int j = 0; j < 8; j++)
                mma_bf16(acc[mf][j], A[mf], Bf[j]);
    }

    // ---- epilogue ----
    const int c0 = nbase + (lane & 3) * 2;
    #pragma unroll
    for (int mf = 0; mf < 2; mf++) {
        #pragma unroll
        for (int hr = 0; hr < 2; hr++) {
            const int rl = mbase + mf * 16 + (lane >> 2) + hr * 8;   // local agent row
            const float a2 = a2s[rl];
            const int agent = hid * 128 + rl;
            if (mode == 0) {
                float* dst = g_d2s + (size_t)agent * SAMPLE_N + n0;
                #pragma unroll
                for (int j = 0; j < 8; j++) {
                    const int col = c0 + j * 8;
                    float d2a = fmaxf(a2 + e2s[col]     - 2.0f * acc[mf][j][hr * 2],     1e-12f);
                    float d2b = fmaxf(a2 + e2s[col + 1] - 2.0f * acc[mf][j][hr * 2 + 1], 1e-12f);
                    *(float2*)(dst + col) = make_float2(d2a, d2b);
                }
            } else {
                const float T = ths[rl];
                #pragma unroll
                for (int j = 0; j < 8; j++) {
                    const int col = c0 + j * 8;
                    float d2a = fmaxf(a2 + e2s[col]     - 2.0f * acc[mf][j][hr * 2],     1e-12f);
                    float d2b = fmaxf(a2 + e2s[col + 1] - 2.0f * acc[mf][j][hr * 2 + 1], 1e-12f);
                    if (d2a < T) { int p = atomicAdd(&scnt[rl], 1); if (p < SLOTS) scand[rl * SLOTS + p] = d2a; }
                    if (d2b < T) { int p = atomicAdd(&scnt[rl], 1); if (p < SLOTS) scand[rl * SLOTS + p] = d2b; }
                }
            }
        }
    }

    if (mode == 1) {
        __syncthreads();
        if (tid < 128) {
            const int agent = hid * 128 + tid;
            uint4* dst = (uint4*)(g_cand + ((size_t)tile * BATCH + agent) * SLOTS);
            const uint4* src = (const uint4*)(scand + tid * SLOTS);
            #pragma unroll
            for (int i = 0; i < SLOTS / 4; i++) dst[i] = src[i];
        }
    }
}

// ---------------- K3: per-row sample threshold (radix-select rank SRANK) -----
__global__ void __launch_bounds__(256) thresh_kernel() {
    extern __shared__ float sv[];  // SAMPLE_N floats
    __shared__ unsigned int hist[256];
    __shared__ unsigned int s_pref;
    __shared__ int s_rank;
    const int b = blockIdx.x, t = threadIdx.x;
    {
        const float4* src = (const float4*)(g_d2s + (size_t)b * SAMPLE_N);
        float4* dst = (float4*)sv;
        for (int i = t; i < SAMPLE_N / 4; i += 256) dst[i] = src[i];
    }
    if (t == 0) { s_pref = 0u; s_rank = SRANK; }
    __syncthreads();
    for (int pass = 3; pass >= 0; pass--) {
        int shift = pass * 8;
        hist[t] = 0u;
        __syncthreads();
        unsigned int pref = s_pref;
        for (int i = t; i < SAMPLE_N; i += 256) {
            unsigned int key = __float_as_uint(sv[i]);
            if (((key >> shift) >> 8) == pref)
                atomicAdd(&hist[(key >> shift) & 255u], 1u);
        }
        __syncthreads();
        radix_pass(hist, &s_pref, &s_rank, t);
    }
    if (t == 0) g_thresh[b] = __uint_as_float(s_pref);
}

// ---------------- K4: final exact select over candidates + reward -----------
__global__ void __launch_bounds__(256) final_kernel(const float* __restrict__ wts,
                                                    float* __restrict__ out) {
    extern __shared__ float sv[];  // CANDTOT floats
    __shared__ unsigned int hist[256];
    __shared__ unsigned int s_pref;
    __shared__ int s_rank;
    __shared__ float s_f[256];
    __shared__ int s_i[256];
    __shared__ float s_w;
    __shared__ double s_r;
    __shared__ int s_m;
    const int b = blockIdx.x, t = threadIdx.x;

    // gather candidates, 16B chunks (SLOTS = 12 floats = 3 x uint4)
    for (int idx = t; idx < NTILES * 3; idx += 256) {
        int tl = idx / 3, q = idx % 3;
        ((uint4*)sv)[(size_t)tl * 3 + q] =
            *(const uint4*)(g_cand + ((size_t)tl * BATCH + b) * SLOTS + q * 4);
    }
    if (t == 0) {
        float w = wts[0];
        double targ = 1.0 / 1000.0 - 1e-6;
        int m = (int)(targ / (double)w);
        double r = targ - (double)m * (double)w;
        if (r <= 0.0) { m -= 1; r = (double)w; }
        s_w = w; s_m = m; s_r = r;
        s_pref = 0u; s_rank = m;
    }
    __syncthreads();

    for (int pass = 3; pass >= 0; pass--) {
        int shift = pass * 8;
        hist[t] = 0u;
        __syncthreads();
        unsigned int pref = s_pref;
        for (int i = t; i < CANDTOT; i += 256) {
            unsigned int key = __float_as_uint(sv[i]);
            if (((key >> shift) >> 8) == pref)
                atomicAdd(&hist[(key >> shift) & 255u], 1u);
        }
        __syncthreads();
        radix_pass(hist, &s_pref, &s_rank, t);
    }

    unsigned int Tkey = s_pref;
    float Tval = __uint_as_float(Tkey);
    int c = 0;
    float ss = 0.0f;
    for (int i = t; i < CANDTOT; i += 256) {
        float v = sv[i];
        if (__float_as_uint(v) < Tkey) { c++; ss += sqrtf(v); }
    }
    s_f[t] = ss; s_i[t] = c;
    __syncthreads();
    for (int off = 128; off > 0; off >>= 1) {
        if (t < off) { s_f[t] += s_f[t + off]; s_i[t] += s_i[t + off]; }
        __syncthreads();
    }
    if (t == 0) {
        double w = (double)s_w;
        double dT = sqrt((double)Tval);
        double cost = w * (double)s_f[0] + (w * (double)(s_m - s_i[0]) + s_r) * dT;
        double BW = 5000.0 / sqrt(128.0);
        out[b] = (float)(5.0 * exp(-BW * cost));
    }
}

// ---------------- launch ----------------
extern "C" void kernel_launch(void* const* d_in, const int* in_sizes, int n_in,
                              void* d_out, int out_size) {
    const float* state   = (const float*)d_in[0];
    const float* action  = (const float*)d_in[1];
    const float* experts = (const float*)d_in[2];
    const float* wts     = (const float*)d_in[3];
    // d_in[4] = scaler_mean: cancels algebraically
    const float* sstd    = (const float*)d_in[5];
    float* out = (float*)d_out;

    cudaFuncSetAttribute(gemm_kernel,   cudaFuncAttributeMaxDynamicSharedMemorySize, GEMM_SMEM);
    cudaFuncSetAttribute(thresh_kernel, cudaFuncAttributeMaxDynamicSharedMemorySize, SAMPLE_N * 4);
    cudaFuncSetAttribute(final_kernel,  cudaFuncAttributeMaxDynamicSharedMemorySize, CANDTOT * 4);

    prep_agent_kernel<<<BATCH, DIM>>>(state, action, sstd);
    gemm_kernel<<<dim3(2, STILES), 256, GEMM_SMEM>>>(experts, 0);
    thresh_kernel<<<BATCH, 256, SAMPLE_N * 4>>>();
    gemm_kernel<<<dim3(2, NTILES), 256, GEMM_SMEM>>>(experts, 1);
    final_kernel<<<BATCH, 256, CANDTOT * 4>>>(wts, out);
}

// round 7
// speedup vs baseline: 3.8583x; 1.1248x over previous
#include <cuda_runtime.h>
#include <cuda_bf16.h>
#include <math.h>
#include <float.h>
#include <stdint.h>

#define BATCH 256
#define NEXP  200000
#define DIM   128
#define DS    96
#define DA    32

#define TILE_N   256
#define NTILES   782                  // ceil(200000/256)
#define STILES   49
#define SAMPLE_N (STILES * TILE_N)    // 12544
#define SRANK    63                   // 0-based sample rank for threshold
#define SLOTS    16
#define CANDTOT  (NTILES * SLOTS)     // 12512

#define PITCH 136                     // bf16 elems per smem row (128 + 8 pad)

// ---------------- static device scratch ----------------
__device__ float          g_a2w[BATCH];
__device__ float          g_inv[DIM];                    // 1/std^2
__device__ __nv_bfloat16  g_abf[BATCH * DIM];            // (a/s^2) in bf16
__device__ float          g_d2s[(size_t)BATCH * SAMPLE_N];  // row-major [b][i]
__device__ float          g_thresh[BATCH];
__device__ float          g_cand[(size_t)NTILES * BATCH * SLOTS];

// ---------------- helpers ----------------
__device__ __forceinline__ uint32_t smem_u32(const void* p) {
    uint32_t a;
    asm("{ .reg .u64 t; cvta.to.shared.u64 t, %1; cvt.u32.u64 %0, t; }" : "=r"(a) : "l"(p));
    return a;
}
__device__ __forceinline__ void ldm_x4(uint32_t& r0, uint32_t& r1, uint32_t& r2, uint32_t& r3,
                                       uint32_t addr) {
    asm volatile("ldmatrix.sync.aligned.m8n8.x4.shared.b16 {%0,%1,%2,%3}, [%4];"
                 : "=r"(r0), "=r"(r1), "=r"(r2), "=r"(r3) : "r"(addr));
}
__device__ __forceinline__ void mma_bf16(float* d, const uint32_t* a, const uint32_t* b) {
    asm volatile("mma.sync.aligned.m16n8k16.row.col.f32.bf16.bf16.f32 "
                 "{%0,%1,%2,%3}, {%4,%5,%6,%7}, {%8,%9}, {%0,%1,%2,%3};"
                 : "+f"(d[0]), "+f"(d[1]), "+f"(d[2]), "+f"(d[3])
                 : "r"(a[0]), "r"(a[1]), "r"(a[2]), "r"(a[3]), "r"(b[0]), "r"(b[1]));
}
__device__ __forceinline__ uint32_t bf2u(float lo, float hi) {
    __nv_bfloat162 b = __floats2bfloat162_rn(lo, hi);
    return *reinterpret_cast<uint32_t*>(&b);
}

// parallel radix-select step: hist[256] filled; update (pref, rank) for this byte.
__device__ __forceinline__ void radix_pass(unsigned int* hist, unsigned int* s_pref,
                                           int* s_rank, int t) {
    __shared__ unsigned int wsum[8];
    const int lane = t & 31, wp = t >> 5;
    unsigned int v = hist[t];
    unsigned int inc = v;
    #pragma unroll
    for (int o = 1; o < 32; o <<= 1) {
        unsigned int u = __shfl_up_sync(0xffffffffu, inc, o);
        if (lane >= o) inc += u;
    }
    if (lane == 31) wsum[wp] = inc;
    __syncthreads();
    unsigned int base = 0;
    #pragma unroll
    for (int i = 0; i < 8; i++) if (i < wp) base += wsum[i];
    const unsigned int incl = inc + base;
    const unsigned int excl = incl - v;
    const int r = *s_rank;
    __syncthreads();
    if ((unsigned)r >= excl && (unsigned)r < incl) {
        *s_rank = r - (int)excl;
        *s_pref = (*s_pref << 8) | (unsigned)t;
    }
    __syncthreads();
}

// ---------------- K0: agent prep ----------------
__global__ void prep_agent_kernel(const float* __restrict__ state,
                                  const float* __restrict__ action,
                                  const float* __restrict__ sstd) {
    __shared__ float red[DIM];
    int b = blockIdx.x, d = threadIdx.x;
    float a = (d < DS) ? state[b * DS + d] : action[b * DA + (d - DS)];
    float s = sstd[d];
    float inv = 1.0f / (s * s);
    float awv = a * inv;
    g_abf[b * DIM + d] = __float2bfloat16_rn(awv);
    if (b == 0) g_inv[d] = inv;
    red[d] = awv * a;
    __syncthreads();
    for (int off = 64; off > 0; off >>= 1) {
        if (d < off) red[d] += red[d + off];
        __syncthreads();
    }
    if (d == 0) g_a2w[b] = red[0];
}

// ---------------- K2: HMMA bf16 GEMM (mode 0: sample d2, mode 1: filtered) ----
// smem layout (bytes)
#define OFF_A    0                              // 128*272 = 34816
#define OFF_B    34816                          // 256*272 = 69632
#define OFF_E2   104448                         // 256*4
#define OFF_A2   105472                         // 128*4 (+pad)
#define OFF_TH   105984
#define OFF_CNT  106496
#define OFF_INV  107008                         // 128*4
#define OFF_CAND 107520                         // 128*16*4 = 8192
#define GEMM_SMEM 115712

__global__ void __launch_bounds__(256, 1)
gemm_kernel(const float* __restrict__ experts, int mode) {
    extern __shared__ __align__(16) char sm[];
    const uint32_t smb = smem_u32(sm);
    const int tid = threadIdx.x, w = tid >> 5, lane = tid & 31;
    const int hid = blockIdx.x;                // agent half: 0 or 1
    const int tile = blockIdx.y;
    const int n0 = tile * TILE_N;

    float* e2s  = (float*)(sm + OFF_E2);
    float* a2s  = (float*)(sm + OFF_A2);
    float* ths  = (float*)(sm + OFF_TH);
    int*   scnt = (int*)(sm + OFF_CNT);
    float* sinv = (float*)(sm + OFF_INV);
    float* scand = (float*)(sm + OFF_CAND);

    if (tid < 128) {
        sinv[tid] = g_inv[tid];
        a2s[tid] = g_a2w[hid * 128 + tid];
        ths[tid] = g_thresh[hid * 128 + tid];
        scnt[tid] = 0;
    }
    #pragma unroll
    for (int s = tid; s < 128 * SLOTS; s += 256) scand[s] = FLT_MAX;

    // ---- A tile (bf16, 128 rows): 2 threads/row, 128B each ----
    {
        int r = tid >> 1, h = (tid & 1) * 8;
        const uint4* asrc = (const uint4*)(g_abf + (size_t)(hid * 128 + r) * DIM) + h;
        uint4* adst = (uint4*)(sm + OFF_A + r * PITCH * 2 + h * 16);
        #pragma unroll
        for (int i = 0; i < 8; i++) adst[i] = asrc[i];
    }
    __syncthreads();   // sinv ready before E loader uses it

    // ---- E tile (256 rows): coalesced fp32 -> bf16 + per-row weighted norm ----
    {
        const int lane8 = lane & 7, lrow = lane >> 3;   // col group, row-in-4
        #pragma unroll
        for (int it = 0; it < 8; it++) {
            const int r = it * 32 + w * 4 + lrow;
            const int n = n0 + r;
            const bool ok = (n < NEXP);
            const float* src = experts + (size_t)n * DIM;
            float part = 0.f;
            #pragma unroll
            for (int s = 0; s < 4; s++) {
                const int cf = s * 32 + lane8 * 4;
                float4 f = ok ? __ldg((const float4*)(src + cf)) : make_float4(0.f, 0.f, 0.f, 0.f);
                const float4 wv = *(const float4*)(sinv + cf);
                part += f.x * f.x * wv.x + f.y * f.y * wv.y + f.z * f.z * wv.z + f.w * f.w * wv.w;
                uint2 o = make_uint2(bf2u(f.x, f.y), bf2u(f.z, f.w));
                *(uint2*)(sm + OFF_B + (r * PITCH + cf) * 2) = o;
            }
            part += __shfl_xor_sync(0xffffffffu, part, 1);
            part += __shfl_xor_sync(0xffffffffu, part, 2);
            part += __shfl_xor_sync(0xffffffffu, part, 4);
            if (lane8 == 0) e2s[r] = ok ? part : 1e30f;
        }
    }
    __syncthreads();

    // ---- warp tile: 64 (M) x 64 (N); warps 2 (M) x 4 (N) ----
    const int mbase = (w >> 2) * 64, nbase = (w & 3) * 64;

    const uint32_t a_addr0 = smb + OFF_A +
        (uint32_t)(((mbase + (lane & 15)) * PITCH + (lane >> 4) * 8) * 2);
    const uint32_t b_addr0 = smb + OFF_B +
        (uint32_t)(((nbase + (lane >> 4) * 8 + (lane & 7)) * PITCH + ((lane >> 3) & 1) * 8) * 2);

    float acc[4][8][4];
    #pragma unroll
    for (int mf = 0; mf < 4; mf++)
        #pragma unroll
        for (int j = 0; j < 8; j++)
            #pragma unroll
            for (int q = 0; q < 4; q++) acc[mf][j][q] = 0.f;

    #pragma unroll
    for (int k = 0; k < 8; k++) {
        const uint32_t koff = (uint32_t)(k * 32);   // 16 bf16 = 32B
        uint32_t A[4][4];
        #pragma unroll
        for (int mf = 0; mf < 4; mf++)
            ldm_x4(A[mf][0], A[mf][1], A[mf][2], A[mf][3],
                   a_addr0 + koff + (uint32_t)(mf * 16 * PITCH * 2));
        uint32_t Bf[8][2];
        #pragma unroll
        for (int jj = 0; jj < 4; jj++) {
            uint32_t r0, r1, r2, r3;
            ldm_x4(r0, r1, r2, r3, b_addr0 + koff + (uint32_t)(jj * 16 * PITCH * 2));
            Bf[jj * 2][0] = r0; Bf[jj * 2][1] = r1;
            Bf[jj * 2 + 1][0] = r2; Bf[jj * 2 + 1][1] = r3;
        }
        #pragma unroll
        for (int mf = 0; mf < 4; mf++)
            #pragma unroll
            for (int j = 0; j < 8; j++)
                mma_bf16(acc[mf][j], A[mf], Bf[j]);
    }

    // ---- epilogue ----
    const int c0 = nbase + (lane & 3) * 2;
    #pragma unroll
    for (int mf = 0; mf < 4; mf++) {
        #pragma unroll
        for (int hr = 0; hr < 2; hr++) {
            const int rl = mbase + mf * 16 + (lane >> 2) + hr * 8;   // local agent row
            const float a2 = a2s[rl];
            const int agent = hid * 128 + rl;
            if (mode == 0) {
                float* dst = g_d2s + (size_t)agent * SAMPLE_N + n0;
                #pragma unroll
                for (int j = 0; j < 8; j++) {
                    const int col = c0 + j * 8;
                    float d2a = fmaxf(a2 + e2s[col]     - 2.0f * acc[mf][j][hr * 2],     1e-12f);
                    float d2b = fmaxf(a2 + e2s[col + 1] - 2.0f * acc[mf][j][hr * 2 + 1], 1e-12f);
                    *(float2*)(dst + col) = make_float2(d2a, d2b);
                }
            } else {
                const float T = ths[rl];
                #pragma unroll
                for (int j = 0; j < 8; j++) {
                    const int col = c0 + j * 8;
                    float d2a = fmaxf(a2 + e2s[col]     - 2.0f * acc[mf][j][hr * 2],     1e-12f);
                    float d2b = fmaxf(a2 + e2s[col + 1] - 2.0f * acc[mf][j][hr * 2 + 1], 1e-12f);
                    if (d2a < T) { int p = atomicAdd(&scnt[rl], 1); if (p < SLOTS) scand[rl * SLOTS + p] = d2a; }
                    if (d2b < T) { int p = atomicAdd(&scnt[rl], 1); if (p < SLOTS) scand[rl * SLOTS + p] = d2b; }
                }
            }
        }
    }

    if (mode == 1) {
        __syncthreads();
        if (tid < 128) {
            const int agent = hid * 128 + tid;
            uint4* dst = (uint4*)(g_cand + ((size_t)tile * BATCH + agent) * SLOTS);
            const uint4* src = (const uint4*)(scand + tid * SLOTS);
            #pragma unroll
            for (int i = 0; i < SLOTS / 4; i++) dst[i] = src[i];
        }
    }
}

// ---------------- K3: per-row sample threshold (radix-select rank SRANK) -----
__global__ void __launch_bounds__(256) thresh_kernel() {
    extern __shared__ float sv[];  // SAMPLE_N floats
    __shared__ unsigned int hist[256];
    __shared__ unsigned int s_pref;
    __shared__ int s_rank;
    const int b = blockIdx.x, t = threadIdx.x;
    {
        const float4* src = (const float4*)(g_d2s + (size_t)b * SAMPLE_N);
        float4* dst = (float4*)sv;
        for (int i = t; i < SAMPLE_N / 4; i += 256) dst[i] = src[i];
    }
    if (t == 0) { s_pref = 0u; s_rank = SRANK; }
    __syncthreads();
    for (int pass = 3; pass >= 0; pass--) {
        int shift = pass * 8;
        hist[t] = 0u;
        __syncthreads();
        unsigned int pref = s_pref;
        for (int i = t; i < SAMPLE_N; i += 256) {
            unsigned int key = __float_as_uint(sv[i]);
            if (((key >> shift) >> 8) == pref)
                atomicAdd(&hist[(key >> shift) & 255u], 1u);
        }
        __syncthreads();
        radix_pass(hist, &s_pref, &s_rank, t);
    }
    if (t == 0) g_thresh[b] = __uint_as_float(s_pref);
}

// ---------------- K4: final exact select over candidates + reward -----------
__global__ void __launch_bounds__(256) final_kernel(const float* __restrict__ wts,
                                                    float* __restrict__ out) {
    extern __shared__ float sv[];  // CANDTOT floats
    __shared__ unsigned int hist[256];
    __shared__ unsigned int s_pref;
    __shared__ int s_rank;
    __shared__ float s_f[256];
    __shared__ int s_i[256];
    __shared__ float s_w;
    __shared__ double s_r;
    __shared__ int s_m;
    const int b = blockIdx.x, t = threadIdx.x;

    // gather candidates, 16B chunks (SLOTS = 16 floats = 4 x uint4)
    for (int idx = t; idx < NTILES * 4; idx += 256) {
        int tl = idx >> 2, q = idx & 3;
        ((uint4*)sv)[(size_t)tl * 4 + q] =
            *(const uint4*)(g_cand + ((size_t)tl * BATCH + b) * SLOTS + q * 4);
    }
    if (t == 0) {
        float w = wts[0];
        double targ = 1.0 / 1000.0 - 1e-6;
        int m = (int)(targ / (double)w);
        double r = targ - (double)m * (double)w;
        if (r <= 0.0) { m -= 1; r = (double)w; }
        s_w = w; s_m = m; s_r = r;
        s_pref = 0u; s_rank = m;
    }
    __syncthreads();

    for (int pass = 3; pass >= 0; pass--) {
        int shift = pass * 8;
        hist[t] = 0u;
        __syncthreads();
        unsigned int pref = s_pref;
        for (int i = t; i < CANDTOT; i += 256) {
            unsigned int key = __float_as_uint(sv[i]);
            if (((key >> shift) >> 8) == pref)
                atomicAdd(&hist[(key >> shift) & 255u], 1u);
        }
        __syncthreads();
        radix_pass(hist, &s_pref, &s_rank, t);
    }

    unsigned int Tkey = s_pref;
    float Tval = __uint_as_float(Tkey);
    int c = 0;
    float ss = 0.0f;
    for (int i = t; i < CANDTOT; i += 256) {
        float v = sv[i];
        if (__float_as_uint(v) < Tkey) { c++; ss += sqrtf(v); }
    }
    s_f[t] = ss; s_i[t] = c;
    __syncthreads();
    for (int off = 128; off > 0; off >>= 1) {
        if (t < off) { s_f[t] += s_f[t + off]; s_i[t] += s_i[t + off]; }
        __syncthreads();
    }
    if (t == 0) {
        double w = (double)s_w;
        double dT = sqrt((double)Tval);
        double cost = w * (double)s_f[0] + (w * (double)(s_m - s_i[0]) + s_r) * dT;
        double BW = 5000.0 / sqrt(128.0);
        out[b] = (float)(5.0 * exp(-BW * cost));
    }
}

// ---------------- launch ----------------
extern "C" void kernel_launch(void* const* d_in, const int* in_sizes, int n_in,
                              void* d_out, int out_size) {
    const float* state   = (const float*)d_in[0];
    const float* action  = (const float*)d_in[1];
    const float* experts = (const float*)d_in[2];
    const float* wts     = (const float*)d_in[3];
    // d_in[4] = scaler_mean: cancels algebraically
    const float* sstd    = (const float*)d_in[5];
    float* out = (float*)d_out;

    cudaFuncSetAttribute(gemm_kernel,   cudaFuncAttributeMaxDynamicSharedMemorySize, GEMM_SMEM);
    cudaFuncSetAttribute(thresh_kernel, cudaFuncAttributeMaxDynamicSharedMemorySize, SAMPLE_N * 4);
    cudaFuncSetAttribute(final_kernel,  cudaFuncAttributeMaxDynamicSharedMemorySize, CANDTOT * 4);

    prep_agent_kernel<<<BATCH, DIM>>>(state, action, sstd);
    gemm_kernel<<<dim3(2, STILES), 256, GEMM_SMEM>>>(experts, 0);
    thresh_kernel<<<BATCH, 256, SAMPLE_N * 4>>>();
    gemm_kernel<<<dim3(2, NTILES), 256, GEMM_SMEM>>>(experts, 1);
    final_kernel<<<BATCH, 256, CANDTOT * 4>>>(wts, out);
}

// round 8
// speedup vs baseline: 4.2048x; 1.0898x over previous
#include <cuda_runtime.h>
#include <cuda_bf16.h>
#include <math.h>
#include <float.h>
#include <stdint.h>

#define BATCH 256
#define NEXP  200000
#define DIM   128
#define DS    96
#define DA    32

#define TILE_N   128
#define NTILES   1563                 // ceil(200000/128)
#define STILES   98
#define SAMPLE_N (STILES * TILE_N)    // 12544
#define SRANK    63                   // 0-based sample rank for threshold
#define SLOTS    12
#define CANDTOT  (NTILES * SLOTS)     // 18756

#define PITCH 136                     // bf16 elems per smem row (128 + 8 pad)

// ---------------- static device scratch ----------------
__device__ float          g_a2w[BATCH];
__device__ float          g_inv[DIM];                    // 1/std^2
__device__ __nv_bfloat16  g_abf[BATCH * DIM];            // (a/s^2) in bf16
__device__ float          g_d2s[(size_t)BATCH * SAMPLE_N];  // row-major [b][i]
__device__ float          g_thresh[BATCH];
__device__ float          g_cand[(size_t)NTILES * BATCH * SLOTS];

// ---------------- helpers ----------------
__device__ __forceinline__ uint32_t smem_u32(const void* p) {
    uint32_t a;
    asm("{ .reg .u64 t; cvta.to.shared.u64 t, %1; cvt.u32.u64 %0, t; }" : "=r"(a) : "l"(p));
    return a;
}
__device__ __forceinline__ void ldm_x4(uint32_t& r0, uint32_t& r1, uint32_t& r2, uint32_t& r3,
                                       uint32_t addr) {
    asm volatile("ldmatrix.sync.aligned.m8n8.x4.shared.b16 {%0,%1,%2,%3}, [%4];"
                 : "=r"(r0), "=r"(r1), "=r"(r2), "=r"(r3) : "r"(addr));
}
__device__ __forceinline__ void mma_bf16(float* d, const uint32_t* a, const uint32_t* b) {
    asm volatile("mma.sync.aligned.m16n8k16.row.col.f32.bf16.bf16.f32 "
                 "{%0,%1,%2,%3}, {%4,%5,%6,%7}, {%8,%9}, {%0,%1,%2,%3};"
                 : "+f"(d[0]), "+f"(d[1]), "+f"(d[2]), "+f"(d[3])
                 : "r"(a[0]), "r"(a[1]), "r"(a[2]), "r"(a[3]), "r"(b[0]), "r"(b[1]));
}
__device__ __forceinline__ uint32_t bf2u(float lo, float hi) {
    __nv_bfloat162 b = __floats2bfloat162_rn(lo, hi);
    return *reinterpret_cast<uint32_t*>(&b);
}

// parallel radix-select step: hist[256] filled; update (pref, rank) for this byte.
__device__ __forceinline__ void radix_pass(unsigned int* hist, unsigned int* s_pref,
                                           int* s_rank, int t) {
    __shared__ unsigned int wsum[8];
    const int lane = t & 31, wp = t >> 5;
    unsigned int v = hist[t];
    unsigned int inc = v;
    #pragma unroll
    for (int o = 1; o < 32; o <<= 1) {
        unsigned int u = __shfl_up_sync(0xffffffffu, inc, o);
        if (lane >= o) inc += u;
    }
    if (lane == 31) wsum[wp] = inc;
    __syncthreads();
    unsigned int base = 0;
    #pragma unroll
    for (int i = 0; i < 8; i++) if (i < wp) base += wsum[i];
    const unsigned int incl = inc + base;
    const unsigned int excl = incl - v;
    const int r = *s_rank;
    __syncthreads();
    if ((unsigned)r >= excl && (unsigned)r < incl) {
        *s_rank = r - (int)excl;
        *s_pref = (*s_pref << 8) | (unsigned)t;
    }
    __syncthreads();
}

// ---------------- K0: agent prep ----------------
__global__ void prep_agent_kernel(const float* __restrict__ state,
                                  const float* __restrict__ action,
                                  const float* __restrict__ sstd) {
    __shared__ float red[DIM];
    int b = blockIdx.x, d = threadIdx.x;
    float a = (d < DS) ? state[b * DS + d] : action[b * DA + (d - DS)];
    float s = sstd[d];
    float inv = 1.0f / (s * s);
    float awv = a * inv;
    g_abf[b * DIM + d] = __float2bfloat16_rn(awv);
    if (b == 0) g_inv[d] = inv;
    red[d] = awv * a;
    __syncthreads();
    for (int off = 64; off > 0; off >>= 1) {
        if (d < off) red[d] += red[d + off];
        __syncthreads();
    }
    if (d == 0) g_a2w[b] = red[0];
}

// ---------------- K2: HMMA bf16 GEMM (mode 0: sample d2, mode 1: filtered) ----
// smem layout (bytes)
#define OFF_A    0                              // 128*272 = 34816
#define OFF_B    34816                          // 128*272 = 34816
#define OFF_E2   69632                          // 128*4
#define OFF_A2   70144
#define OFF_TH   70656
#define OFF_CNT  71168
#define OFF_INV  71680
#define OFF_CAND 72192                          // 128*12*4 = 6144
#define GEMM_SMEM 78336

__global__ void __launch_bounds__(256, 2)
gemm_kernel(const float* __restrict__ experts, int mode) {
    extern __shared__ __align__(16) char sm[];
    const uint32_t smb = smem_u32(sm);
    const int tid = threadIdx.x, w = tid >> 5, lane = tid & 31;
    const int hid = blockIdx.x;                // agent half: 0 or 1
    const int tile = blockIdx.y;
    const int n0 = tile * TILE_N;

    float* e2s  = (float*)(sm + OFF_E2);
    float* a2s  = (float*)(sm + OFF_A2);
    float* ths  = (float*)(sm + OFF_TH);
    int*   scnt = (int*)(sm + OFF_CNT);
    float* sinv = (float*)(sm + OFF_INV);
    float* scand = (float*)(sm + OFF_CAND);

    if (tid < 128) {
        sinv[tid] = g_inv[tid];
        a2s[tid] = g_a2w[hid * 128 + tid];
        ths[tid] = g_thresh[hid * 128 + tid];
        scnt[tid] = 0;
    }
    #pragma unroll
    for (int s = tid; s < 128 * SLOTS; s += 256) scand[s] = FLT_MAX;

    // ---- A tile (bf16, 128 rows): 2 threads/row, 128B each ----
    {
        int r = tid >> 1, h = (tid & 1) * 8;
        const uint4* asrc = (const uint4*)(g_abf + (size_t)(hid * 128 + r) * DIM) + h;
        uint4* adst = (uint4*)(sm + OFF_A + r * PITCH * 2 + h * 16);
        #pragma unroll
        for (int i = 0; i < 8; i++) adst[i] = asrc[i];
    }
    __syncthreads();   // sinv ready before E loader uses it

    // ---- E tile (128 rows): coalesced fp32 -> bf16 + per-row weighted norm ----
    {
        const int lane8 = lane & 7, lrow = lane >> 3;   // col group, row-in-4
        #pragma unroll
        for (int it = 0; it < 4; it++) {
            const int r = it * 32 + w * 4 + lrow;
            const int n = n0 + r;
            const bool ok = (n < NEXP);
            const float* src = experts + (size_t)n * DIM;
            float part = 0.f;
            #pragma unroll
            for (int s = 0; s < 4; s++) {
                const int cf = s * 32 + lane8 * 4;
                float4 f = ok ? __ldg((const float4*)(src + cf)) : make_float4(0.f, 0.f, 0.f, 0.f);
                const float4 wv = *(const float4*)(sinv + cf);
                part += f.x * f.x * wv.x + f.y * f.y * wv.y + f.z * f.z * wv.z + f.w * f.w * wv.w;
                uint2 o = make_uint2(bf2u(f.x, f.y), bf2u(f.z, f.w));
                *(uint2*)(sm + OFF_B + (r * PITCH + cf) * 2) = o;
            }
            part += __shfl_xor_sync(0xffffffffu, part, 1);
            part += __shfl_xor_sync(0xffffffffu, part, 2);
            part += __shfl_xor_sync(0xffffffffu, part, 4);
            if (lane8 == 0) e2s[r] = ok ? part : 1e30f;
        }
    }
    __syncthreads();

    // ---- warp tile: 32 (M) x 64 (N); warps 4 (M) x 2 (N) ----
    const int mbase = (w >> 1) * 32, nbase = (w & 1) * 64;

    const uint32_t a_addr0 = smb + OFF_A +
        (uint32_t)(((mbase + (lane & 15)) * PITCH + (lane >> 4) * 8) * 2);
    const uint32_t b_addr0 = smb + OFF_B +
        (uint32_t)(((nbase + (lane >> 4) * 8 + (lane & 7)) * PITCH + ((lane >> 3) & 1) * 8) * 2);

    float acc[2][8][4];
    #pragma unroll
    for (int mf = 0; mf < 2; mf++)
        #pragma unroll
        for (int j = 0; j < 8; j++)
            #pragma unroll
            for (int q = 0; q < 4; q++) acc[mf][j][q] = 0.f;

    #pragma unroll
    for (int k = 0; k < 8; k++) {
        const uint32_t koff = (uint32_t)(k * 32);   // 16 bf16 = 32B
        uint32_t A[2][4];
        ldm_x4(A[0][0], A[0][1], A[0][2], A[0][3], a_addr0 + koff);
        ldm_x4(A[1][0], A[1][1], A[1][2], A[1][3], a_addr0 + koff + 16 * PITCH * 2);
        uint32_t Bf[8][2];
        #pragma unroll
        for (int jj = 0; jj < 4; jj++) {
            uint32_t r0, r1, r2, r3;
            ldm_x4(r0, r1, r2, r3, b_addr0 + koff + (uint32_t)(jj * 16 * PITCH * 2));
            Bf[jj * 2][0] = r0; Bf[jj * 2][1] = r1;
            Bf[jj * 2 + 1][0] = r2; Bf[jj * 2 + 1][1] = r3;
        }
        #pragma unroll
        for (int mf = 0; mf < 2; mf++)
            #pragma unroll
            for (int j = 0; j < 8; j++)
                mma_bf16(acc[mf][j], A[mf], Bf[j]);
    }

    // ---- epilogue ----
    const int c0 = nbase + (lane & 3) * 2;
    #pragma unroll
    for (int mf = 0; mf < 2; mf++) {
        #pragma unroll
        for (int hr = 0; hr < 2; hr++) {
            const int rl = mbase + mf * 16 + (lane >> 2) + hr * 8;   // local agent row
            const float a2 = a2s[rl];
            const int agent = hid * 128 + rl;
            if (mode == 0) {
                float* dst = g_d2s + (size_t)agent * SAMPLE_N + n0;
                #pragma unroll
                for (int j = 0; j < 8; j++) {
                    const int col = c0 + j * 8;
                    float d2a = fmaxf(a2 + e2s[col]     - 2.0f * acc[mf][j][hr * 2],     1e-12f);
                    float d2b = fmaxf(a2 + e2s[col + 1] - 2.0f * acc[mf][j][hr * 2 + 1], 1e-12f);
                    *(float2*)(dst + col) = make_float2(d2a, d2b);
                }
            } else {
                const float T = ths[rl];
                #pragma unroll
                for (int j = 0; j < 8; j++) {
                    const int col = c0 + j * 8;
                    float d2a = fmaxf(a2 + e2s[col]     - 2.0f * acc[mf][j][hr * 2],     1e-12f);
                    float d2b = fmaxf(a2 + e2s[col + 1] - 2.0f * acc[mf][j][hr * 2 + 1], 1e-12f);
                    if (d2a < T) { int p = atomicAdd(&scnt[rl], 1); if (p < SLOTS) scand[rl * SLOTS + p] = d2a; }
                    if (d2b < T) { int p = atomicAdd(&scnt[rl], 1); if (p < SLOTS) scand[rl * SLOTS + p] = d2b; }
                }
            }
        }
    }

    if (mode == 1) {
        __syncthreads();
        if (tid < 128) {
            const int agent = hid * 128 + tid;
            uint4* dst = (uint4*)(g_cand + ((size_t)tile * BATCH + agent) * SLOTS);
            const uint4* src = (const uint4*)(scand + tid * SLOTS);
            #pragma unroll
            for (int i = 0; i < SLOTS / 4; i++) dst[i] = src[i];
        }
    }
}

// ---------------- K3: per-row sample threshold (radix-select rank SRANK) -----
__global__ void __launch_bounds__(256) thresh_kernel() {
    extern __shared__ float sv[];  // SAMPLE_N floats
    __shared__ unsigned int hist[256];
    __shared__ unsigned int s_pref;
    __shared__ int s_rank;
    const int b = blockIdx.x, t = threadIdx.x;
    {
        const float4* src = (const float4*)(g_d2s + (size_t)b * SAMPLE_N);
        float4* dst = (float4*)sv;
        for (int i = t; i < SAMPLE_N / 4; i += 256) dst[i] = src[i];
    }
    if (t == 0) { s_pref = 0u; s_rank = SRANK; }
    __syncthreads();
    for (int pass = 3; pass >= 0; pass--) {
        int shift = pass * 8;
        hist[t] = 0u;
        __syncthreads();
        unsigned int pref = s_pref;
        for (int i = t; i < SAMPLE_N; i += 256) {
            unsigned int key = __float_as_uint(sv[i]);
            if (((key >> shift) >> 8) == pref)
                atomicAdd(&hist[(key >> shift) & 255u], 1u);
        }
        __syncthreads();
        radix_pass(hist, &s_pref, &s_rank, t);
    }
    if (t == 0) g_thresh[b] = __uint_as_float(s_pref);
}

// ---------------- K4: final exact select over candidates + reward -----------
__global__ void __launch_bounds__(256) final_kernel(const float* __restrict__ wts,
                                                    float* __restrict__ out) {
    extern __shared__ float sv[];  // CANDTOT floats
    __shared__ unsigned int hist[256];
    __shared__ unsigned int s_pref;
    __shared__ int s_rank;
    __shared__ float s_f[256];
    __shared__ int s_i[256];
    __shared__ float s_w;
    __shared__ double s_r;
    __shared__ int s_m;
    const int b = blockIdx.x, t = threadIdx.x;

    // gather candidates, 16B chunks (SLOTS = 12 floats = 3 x uint4)
    for (int idx = t; idx < NTILES * 3; idx += 256) {
        int tl = idx / 3, q = idx % 3;
        ((uint4*)sv)[(size_t)tl * 3 + q] =
            *(const uint4*)(g_cand + ((size_t)tl * BATCH + b) * SLOTS + q * 4);
    }
    if (t == 0) {
        float w = wts[0];
        double targ = 1.0 / 1000.0 - 1e-6;
        int m = (int)(targ / (double)w);
        double r = targ - (double)m * (double)w;
        if (r <= 0.0) { m -= 1; r = (double)w; }
        s_w = w; s_m = m; s_r = r;
        s_pref = 0u; s_rank = m;
    }
    __syncthreads();

    for (int pass = 3; pass >= 0; pass--) {
        int shift = pass * 8;
        hist[t] = 0u;
        __syncthreads();
        unsigned int pref = s_pref;
        for (int i = t; i < CANDTOT; i += 256) {
            unsigned int key = __float_as_uint(sv[i]);
            if (((key >> shift) >> 8) == pref)
                atomicAdd(&hist[(key >> shift) & 255u], 1u);
        }
        __syncthreads();
        radix_pass(hist, &s_pref, &s_rank, t);
    }

    unsigned int Tkey = s_pref;
    float Tval = __uint_as_float(Tkey);
    int c = 0;
    float ss = 0.0f;
    for (int i = t; i < CANDTOT; i += 256) {
        float v = sv[i];
        if (__float_as_uint(v) < Tkey) { c++; ss += sqrtf(v); }
    }
    s_f[t] = ss; s_i[t] = c;
    __syncthreads();
    for (int off = 128; off > 0; off >>= 1) {
        if (t < off) { s_f[t] += s_f[t + off]; s_i[t] += s_i[t + off]; }
        __syncthreads();
    }
    if (t == 0) {
        double w = (double)s_w;
        double dT = sqrt((double)Tval);
        double cost = w * (double)s_f[0] + (w * (double)(s_m - s_i[0]) + s_r) * dT;
        double BW = 5000.0 / sqrt(128.0);
        out[b] = (float)(5.0 * exp(-BW * cost));
    }
}

// ---------------- launch ----------------
extern "C" void kernel_launch(void* const* d_in, const int* in_sizes, int n_in,
                              void* d_out, int out_size) {
    const float* state   = (const float*)d_in[0];
    const float* action  = (const float*)d_in[1];
    const float* experts = (const float*)d_in[2];
    const float* wts     = (const float*)d_in[3];
    // d_in[4] = scaler_mean: cancels algebraically
    const float* sstd    = (const float*)d_in[5];
    float* out = (float*)d_out;

    cudaFuncSetAttribute(gemm_kernel,   cudaFuncAttributeMaxDynamicSharedMemorySize, GEMM_SMEM);
    cudaFuncSetAttribute(thresh_kernel, cudaFuncAttributeMaxDynamicSharedMemorySize, SAMPLE_N * 4);
    cudaFuncSetAttribute(final_kernel,  cudaFuncAttributeMaxDynamicSharedMemorySize, CANDTOT * 4);

    prep_agent_kernel<<<BATCH, DIM>>>(state, action, sstd);
    gemm_kernel<<<dim3(2, STILES), 256, GEMM_SMEM>>>(experts, 0);
    thresh_kernel<<<BATCH, 256, SAMPLE_N * 4>>>();
    gemm_kernel<<<dim3(2, NTILES), 256, GEMM_SMEM>>>(experts, 1);
    final_kernel<<<BATCH, 256, CANDTOT * 4>>>(wts, out);
}